// round 7
// baseline (speedup 1.0000x reference)
#include <cuda_runtime.h>

#define LMAX 32768
#define NMAX 32768
#define TCB 128    // backward: candidates per smem tile (64 pairs, 2KB)
#define TTF 64     // forward: targets per smem tile (32 pairs, 1KB)
#define CHKP 16    // chunk in PAIRS (32 items) for index rescan
#define QB 6       // k_bwd targets per thread
#define QF 4       // k_fwd empties per thread

#define POSINF __int_as_float(0x7F800000)
#define NEGINF __int_as_float(0xFF800000)

typedef unsigned long long ull;

// ---------------- device scratch (no allocations allowed) ----------------
__device__ unsigned int  g_keys[LMAX];
__device__ unsigned char g_islm[LMAX];
__device__ float         g_thr;
__device__ int           g_count;
__device__ int           g_ecount;
__device__ float4        g_candC[LMAX];     // kept cand: x,y,z, mh=-0.5*|c|^2
__device__ int           g_candIdx[LMAX];   // compacted kept -> original index
__device__ ull           g_bwd[NMAX];       // per target: (sortable(-smax)<<32)|candOrigIdx
__device__ ull           g_fwd[LMAX];       // per cand:   (sortable(-smax)<<32)|tgtIdx
__device__ float         g_num[LMAX * 3];
__device__ float         g_den[LMAX];
__device__ int           g_exact[LMAX];
__device__ float         g_exrgb[LMAX * 3];
__device__ float4        g_eC[LMAX];        // compacted empty cands: x,y,z, bits(origIdx)

// ---------------- helpers ----------------
__device__ __forceinline__ unsigned f2u(float f) {
    unsigned i = __float_as_uint(f);
    return (i & 0x80000000u) ? ~i : (i | 0x80000000u);
}
__device__ __forceinline__ float u2f(unsigned u) {
    unsigned i = (u & 0x80000000u) ? (u & 0x7FFFFFFFu) : ~u;
    return __uint_as_float(i);
}
__device__ __forceinline__ ull fma2(ull a, ull b, ull c) {
    ull d;
    asm("fma.rn.f32x2 %0, %1, %2, %3;" : "=l"(d) : "l"(a), "l"(b), "l"(c));
    return d;
}
__device__ __forceinline__ ull pk2(float lo, float hi) {
    ull r;
    asm("mov.b64 %0, {%1, %2};" : "=l"(r) : "f"(lo), "f"(hi));
    return r;
}
__device__ __forceinline__ void up2(ull v, float& lo, float& hi) {
    asm("mov.b64 {%0, %1}, %2;" : "=f"(lo), "=f"(hi) : "l"(v));
}
__device__ __forceinline__ float lo2(ull v) {
    float lo, hi;
    up2(v, lo, hi);
    return lo;
}

__device__ __forceinline__ float blockReduceSum(float v) {
    __shared__ float sh[32];
    int lane = threadIdx.x & 31, w = threadIdx.x >> 5;
#pragma unroll
    for (int o = 16; o > 0; o >>= 1) v += __shfl_down_sync(0xFFFFFFFFu, v, o);
    if (lane == 0) sh[w] = v;
    __syncthreads();
    v = (threadIdx.x < (blockDim.x >> 5)) ? sh[lane] : 0.f;
    if (w == 0) {
#pragma unroll
        for (int o = 16; o > 0; o >>= 1) v += __shfl_down_sync(0xFFFFFFFFu, v, o);
    }
    return v;
}

// ---------------- kernels ----------------
// init of all scratch + local-max over groups of 8 + sortable keys (fused)
__global__ void k_initprep(const float* __restrict__ pred, float* out, int L, int N) {
    int i = blockIdx.x * blockDim.x + threadIdx.x;
    if (i == 0) { g_count = 0; g_ecount = 0; out[0] = 0.f; out[1] = 0.f; }
    if (i < L) {
        g_num[3 * i] = 0.f; g_num[3 * i + 1] = 0.f; g_num[3 * i + 2] = 0.f;
        g_den[i] = 0.f; g_exact[i] = 0;
        g_fwd[i] = 0xFFFFFFFFFFFFFFFFULL;
    }
    if (i < N) g_bwd[i] = 0xFFFFFFFFFFFFFFFFULL;
    int G = L >> 3;
    if (i < G) {
        const float* p = pred + i * 8;
        float bv = p[0]; int bi = 0;
#pragma unroll
        for (int j = 1; j < 8; j++) { float v = p[j]; if (v > bv) { bv = v; bi = j; } }
#pragma unroll
        for (int j = 0; j < 8; j++) {
            bool lm = (j == bi);
            g_islm[i * 8 + j] = lm ? 1 : 0;
            g_keys[i * 8 + j] = f2u(lm ? POSINF : p[j]);
        }
    }
}

// single-block MSD radix select: threshold = k-th smallest of keys, k = L - points_num
__global__ void k_select(const int* __restrict__ pn, int L) {
    __shared__ unsigned hist[256];
    __shared__ unsigned s_prefix;
    __shared__ int s_rank;
    int tid = threadIdx.x;
    if (tid == 0) { s_prefix = 0u; s_rank = L - pn[0]; }
    __syncthreads();
    for (int round = 0; round < 4; round++) {
        int shift = 24 - 8 * round;
        if (tid < 256) hist[tid] = 0u;
        __syncthreads();
        unsigned pref = s_prefix;
        unsigned mask = (round == 0) ? 0u : (0xFFFFFFFFu << (shift + 8));
        for (int i = tid; i < L; i += blockDim.x) {
            unsigned u = g_keys[i];
            if ((u & mask) == pref) atomicAdd(&hist[(u >> shift) & 0xFFu], 1u);
        }
        __syncthreads();
        if (tid == 0) {
            int r = s_rank; unsigned b = 0;
            while (b < 256u) { int c = (int)hist[b]; if (c >= r) break; r -= c; b++; }
            s_rank = r;
            s_prefix = pref | (b << shift);
        }
        __syncthreads();
    }
    if (tid == 0) g_thr = u2f(s_prefix);
}

// keep mask, BCE (coord loss), warp-aggregated compaction
__global__ void k_keep(const float* __restrict__ pred, const int* __restrict__ kt,
                       const float* __restrict__ cxyz, int L, float* out) {
    int i = blockIdx.x * blockDim.x + threadIdx.x;
    float bce = 0.f; bool keep = false;
    float thr = g_thr;
    if (i < L) {
        float p = pred[i];
        float t = (float)kt[i];
        bce = fmaxf(p, 0.f) - p * t + log1pf(expf(-fabsf(p)));
        keep = (p > thr) || (g_islm[i] != 0);
    }
    unsigned m = __ballot_sync(0xFFFFFFFFu, keep);
    if (keep) {
        int lane = threadIdx.x & 31;
        int leader = __ffs(m) - 1;
        int base = 0;
        if (lane == leader) base = atomicAdd(&g_count, __popc(m));
        base = __shfl_sync(m, base, leader);
        int pos = base + __popc(m & ((1u << lane) - 1u));
        float x = cxyz[3 * i], y = cxyz[3 * i + 1], z = cxyz[3 * i + 2];
        float mh = -0.5f * fmaf(z, z, fmaf(y, y, x * x));
        g_candC[pos] = make_float4(x, y, z, mh);
        g_candIdx[pos] = i;
    }
    float s = blockReduceSum(bce);
    if (threadIdx.x == 0) atomicAdd(out, s);
}

// backward sweep: per target, argmax of s = dot(t,c) - 0.5|c|^2 over kept candidates.
// Candidates pairwise-packed into f32x2 lanes in smem; QB=6 targets/thread (6 independent
// fma2 chains per LDS pair). Chunk max + exact scalar rescan for the index.
__global__ void __launch_bounds__(128) k_bwd(const float* __restrict__ txyz, int N) {
    __shared__ float4 sP[TCB / 2], sQ[TCB / 2];
    int count = g_count;
    int tstart = blockIdx.x * TCB;
    if (tstart >= count) return;
    int tid = threadIdx.x;
    {
        int p = tstart + tid;
        float4 c = (p < count) ? g_candC[p] : make_float4(0.f, 0.f, 0.f, NEGINF);
        int jp = tid >> 1;
        if ((tid & 1) == 0) { sP[jp].x = c.x; sP[jp].z = c.y; sQ[jp].x = c.z; sQ[jp].z = c.w; }
        else                { sP[jp].y = c.x; sP[jp].w = c.y; sQ[jp].y = c.z; sQ[jp].w = c.w; }
    }
    __syncthreads();

    int tbase = blockIdx.y * (128 * QB) + tid;
    ull TX[QB], TY[QB], TZ[QB];
    bool V[QB];
#pragma unroll
    for (int q = 0; q < QB; q++) {
        int t = tbase + 128 * q;
        V[q] = t < N;
        float x = V[q] ? txyz[3 * t] : 0.f;
        float y = V[q] ? txyz[3 * t + 1] : 0.f;
        float z = V[q] ? txyz[3 * t + 2] : 0.f;
        TX[q] = pk2(x, x); TY[q] = pk2(y, y); TZ[q] = pk2(z, z);
    }

    float best[QB];
    int kc[QB];
#pragma unroll
    for (int q = 0; q < QB; q++) { best[q] = NEGINF; kc[q] = 0; }

    for (int cs = 0; cs < TCB / 2; cs += CHKP) {
        float a0[QB], a1[QB];
#pragma unroll
        for (int q = 0; q < QB; q++) { a0[q] = NEGINF; a1[q] = NEGINF; }
#pragma unroll 8
        for (int jp = cs; jp < cs + CHKP; jp++) {
            ulonglong2 qp = *reinterpret_cast<const ulonglong2*>(&sP[jp]);
            ulonglong2 qq = *reinterpret_cast<const ulonglong2*>(&sQ[jp]);
#pragma unroll
            for (int q = 0; q < QB; q++) {
                ull s = fma2(qp.x, TX[q], fma2(qp.y, TY[q], fma2(qq.x, TZ[q], qq.y)));
                float lo, hi;
                up2(s, lo, hi);
                a0[q] = fmaxf(a0[q], lo); a1[q] = fmaxf(a1[q], hi);
            }
        }
#pragma unroll
        for (int q = 0; q < QB; q++) {
            float m = fmaxf(a0[q], a1[q]);
            if (m > best[q]) { best[q] = m; kc[q] = cs; }
        }
    }

#pragma unroll
    for (int q = 0; q < QB; q++) {
        if (!V[q]) continue;
        float x = lo2(TX[q]), y = lo2(TY[q]), z = lo2(TZ[q]);
        int bidx = -1;
        for (int jp = kc[q]; jp < kc[q] + CHKP; jp++) {
            float s0 = fmaf(sP[jp].x, x, fmaf(sP[jp].z, y, fmaf(sQ[jp].x, z, sQ[jp].z)));
            if (s0 == best[q]) { bidx = 2 * jp; break; }
            float s1 = fmaf(sP[jp].y, x, fmaf(sP[jp].w, y, fmaf(sQ[jp].y, z, sQ[jp].w)));
            if (s1 == best[q]) { bidx = 2 * jp + 1; break; }
        }
        if (bidx >= 0) {
            ull pk = ((ull)f2u(-best[q]) << 32) | (unsigned)g_candIdx[tstart + bidx];
            atomicMin(&g_bwd[tbase + 128 * q], pk);
        }
    }
}

// per target: scatter weighted rgb into the winning candidate
__global__ void k_scatter(const float* __restrict__ txyz, const float* __restrict__ trgb, int N) {
    int n = blockIdx.x * blockDim.x + threadIdx.x;
    if (n >= N) return;
    ull pk = g_bwd[n];
    if (pk == 0xFFFFFFFFFFFFFFFFULL) return;
    unsigned u = (unsigned)(pk >> 32);
    int idx = (int)(unsigned)(pk & 0xFFFFFFFFULL);
    float m = u2f(u);  // m = h - dot, d2 = t2 + 2m
    float tx = txyz[3 * n], ty = txyz[3 * n + 1], tz = txyz[3 * n + 2];
    float t2 = fmaf(tz, tz, fmaf(ty, ty, tx * tx));
    float d2 = fmaxf(fmaf(2.f, m, t2), 0.f);
    float r = trgb[3 * n], g = trgb[3 * n + 1], b = trgb[3 * n + 2];
    if (d2 == 0.f) {
        g_exact[idx] = 1;
        g_exrgb[3 * idx] = r; g_exrgb[3 * idx + 1] = g; g_exrgb[3 * idx + 2] = b;
    } else {
        float w = 1.0f / sqrtf(fmaxf(d2, 1e-30f));
        atomicAdd(&g_num[3 * idx],     r * w);
        atomicAdd(&g_num[3 * idx + 1], g * w);
        atomicAdd(&g_num[3 * idx + 2], b * w);
        atomicAdd(&g_den[idx], w);
    }
}

// compact kept candidates that received no color (the "empty" set)
__global__ void k_compactE(int L) {
    int p = blockIdx.x * blockDim.x + threadIdx.x;
    bool e = false; int l = 0;
    float x = 0.f, y = 0.f, z = 0.f;
    if (p < g_count) {
        l = g_candIdx[p];
        if (g_den[l] == 0.f && g_exact[l] == 0) {
            e = true;
            float4 c = g_candC[p];
            x = c.x; y = c.y; z = c.z;
        }
    }
    unsigned m = __ballot_sync(0xFFFFFFFFu, e);
    if (e) {
        int lane = threadIdx.x & 31;
        int leader = __ffs(m) - 1;
        int base = 0;
        if (lane == leader) base = atomicAdd(&g_ecount, __popc(m));
        base = __shfl_sync(m, base, leader);
        int pos = base + __popc(m & ((1u << lane) - 1u));
        g_eC[pos] = make_float4(x, y, z, __int_as_float(l));
    }
}

// forward sweep: per empty candidate, argmax of s = dot(c,t) - 0.5|t|^2 over all targets.
// Targets pairwise-packed in smem; QF=4 empty cands/thread (register-blocked).
__global__ void __launch_bounds__(128) k_fwd(const float* __restrict__ txyz, int N) {
    int ec = g_ecount;
    int estart = blockIdx.x * (128 * QF);
    if (estart >= ec) return;
    __shared__ float4 sP[TTF / 2], sQ[TTF / 2];
    int tid = threadIdx.x;
    int tstart = blockIdx.y * TTF;
    if (tid < TTF) {
        int t = tstart + tid;
        float x = 0.f, y = 0.f, z = 0.f, mh = NEGINF;
        if (t < N) {
            x = txyz[3 * t]; y = txyz[3 * t + 1]; z = txyz[3 * t + 2];
            mh = -0.5f * fmaf(z, z, fmaf(y, y, x * x));
        }
        int jp = tid >> 1;
        if ((tid & 1) == 0) { sP[jp].x = x; sP[jp].z = y; sQ[jp].x = z; sQ[jp].z = mh; }
        else                { sP[jp].y = x; sP[jp].w = y; sQ[jp].y = z; sQ[jp].w = mh; }
    }
    __syncthreads();

    ull CX[QF], CY[QF], CZ[QF];
    int CL[QF];
    bool V[QF];
#pragma unroll
    for (int q = 0; q < QF; q++) {
        int e = estart + tid + 128 * q;
        V[q] = e < ec;
        float4 c = V[q] ? g_eC[e] : make_float4(0.f, 0.f, 0.f, 0.f);
        CX[q] = pk2(c.x, c.x); CY[q] = pk2(c.y, c.y); CZ[q] = pk2(c.z, c.z);
        CL[q] = __float_as_int(c.w);
    }

    float best[QF];
    int kc[QF];
#pragma unroll
    for (int q = 0; q < QF; q++) { best[q] = NEGINF; kc[q] = 0; }

    for (int cs = 0; cs < TTF / 2; cs += CHKP) {
        float a0[QF], a1[QF];
#pragma unroll
        for (int q = 0; q < QF; q++) { a0[q] = NEGINF; a1[q] = NEGINF; }
#pragma unroll 8
        for (int jp = cs; jp < cs + CHKP; jp++) {
            ulonglong2 qp = *reinterpret_cast<const ulonglong2*>(&sP[jp]);
            ulonglong2 qq = *reinterpret_cast<const ulonglong2*>(&sQ[jp]);
#pragma unroll
            for (int q = 0; q < QF; q++) {
                ull s = fma2(qp.x, CX[q], fma2(qp.y, CY[q], fma2(qq.x, CZ[q], qq.y)));
                float lo, hi;
                up2(s, lo, hi);
                a0[q] = fmaxf(a0[q], lo); a1[q] = fmaxf(a1[q], hi);
            }
        }
#pragma unroll
        for (int q = 0; q < QF; q++) {
            float m = fmaxf(a0[q], a1[q]);
            if (m > best[q]) { best[q] = m; kc[q] = cs; }
        }
    }

#pragma unroll
    for (int q = 0; q < QF; q++) {
        if (!V[q]) continue;
        float x = lo2(CX[q]), y = lo2(CY[q]), z = lo2(CZ[q]);
        int bidx = -1;
        for (int jp = kc[q]; jp < kc[q] + CHKP; jp++) {
            float s0 = fmaf(sP[jp].x, x, fmaf(sP[jp].z, y, fmaf(sQ[jp].x, z, sQ[jp].z)));
            if (s0 == best[q]) { bidx = 2 * jp; break; }
            float s1 = fmaf(sP[jp].y, x, fmaf(sP[jp].w, y, fmaf(sQ[jp].y, z, sQ[jp].w)));
            if (s1 == best[q]) { bidx = 2 * jp + 1; break; }
        }
        if (bidx >= 0) {
            ull pk = ((ull)f2u(-best[q]) << 32) | (unsigned)(tstart + bidx);
            atomicMin(&g_fwd[CL[q]], pk);
        }
    }
}

// final L1 loss over kept candidates
__global__ void k_final(const float* __restrict__ crgb, const float* __restrict__ trgb,
                        float* out, int N) {
    int p = blockIdx.x * blockDim.x + threadIdx.x;
    float loss = 0.f;
    if (p < g_count) {
        int l = g_candIdx[p];
        float r0, r1, r2;
        if (g_exact[l]) {
            r0 = g_exrgb[3 * l]; r1 = g_exrgb[3 * l + 1]; r2 = g_exrgb[3 * l + 2];
        } else {
            float den = g_den[l];
            if (den != 0.f) {
                r0 = g_num[3 * l] / den;
                r1 = g_num[3 * l + 1] / den;
                r2 = g_num[3 * l + 2] / den;
            } else {
                ull pk = g_fwd[l];
                unsigned ti = (unsigned)(pk & 0xFFFFFFFFULL);
                if (ti < (unsigned)N) {
                    r0 = trgb[3 * ti]; r1 = trgb[3 * ti + 1]; r2 = trgb[3 * ti + 2];
                } else {
                    r0 = r1 = r2 = 0.f;
                }
            }
        }
        float q0 = crgb[3 * l] * 255.f;
        float q1 = crgb[3 * l + 1] * 255.f;
        float q2 = crgb[3 * l + 2] * 255.f;
        loss = fabsf(q0 - r0) + fabsf(q1 - r1) + fabsf(q2 - r2);
    }
    float s = blockReduceSum(loss);
    if (threadIdx.x == 0) atomicAdd(out + 1, s);
}

// ---------------- launch ----------------
extern "C" void kernel_launch(void* const* d_in, const int* in_sizes, int n_in,
                              void* d_out, int out_size) {
    const float* pred = (const float*)d_in[0];
    const float* cxyz = (const float*)d_in[1];
    const float* crgb = (const float*)d_in[2];
    const float* txyz = (const float*)d_in[3];
    const float* trgb = (const float*)d_in[4];
    const int*   kt   = (const int*)d_in[5];
    const int*   pn   = (const int*)d_in[6];
    float* out = (float*)d_out;

    int L = in_sizes[0];
    int N = in_sizes[3] / 3;
    int M = L > N ? L : N;

    k_initprep<<<(M + 255) / 256, 256>>>(pred, out, L, N);
    k_select<<<1, 1024>>>(pn, L);
    k_keep<<<(L + 255) / 256, 256>>>(pred, kt, cxyz, L, out);
    dim3 gb((L + TCB - 1) / TCB, (N + 128 * QB - 1) / (128 * QB));
    k_bwd<<<gb, 128>>>(txyz, N);
    k_scatter<<<(N + 255) / 256, 256>>>(txyz, trgb, N);
    k_compactE<<<(L + 255) / 256, 256>>>(L);
    dim3 gf((L + 128 * QF - 1) / (128 * QF), (N + TTF - 1) / TTF);
    k_fwd<<<gf, 128>>>(txyz, N);
    k_final<<<(L + 255) / 256, 256>>>(crgb, trgb, out, N);
}